// round 3
// baseline (speedup 1.0000x reference)
#include <cuda_runtime.h>
#include <cuda_bf16.h>
#include <cstdint>

#define H      128
#define NH     8
#define HDIM   16
#define MAXDEG 16
#define NPB    4            // nodes per block in attention kernel
#define MAXN_PAD 50048      // 391 * 128, >= N

// ---------------- scratch (device globals: no allocations allowed) ----------
__device__ float g_Q[MAXN_PAD * H];
__device__ float g_K[MAXN_PAD * H];
__device__ float g_V[MAXN_PAD * H];

// ---------------- packed f32x2 helpers --------------------------------------
__device__ __forceinline__ unsigned long long fma2(unsigned long long a,
                                                   unsigned long long b,
                                                   unsigned long long c) {
    unsigned long long d;
    asm("fma.rn.f32x2 %0, %1, %2, %3;" : "=l"(d) : "l"(a), "l"(b), "l"(c));
    return d;
}
__device__ __forceinline__ unsigned long long dup2(float x) {
    unsigned long long r;
    unsigned int xi = __float_as_uint(x);
    asm("mov.b64 %0, {%1, %1};" : "=l"(r) : "r"(xi));
    return r;
}
__device__ __forceinline__ void unpack2(unsigned long long v, float& lo, float& hi) {
    unsigned int a, b;
    asm("mov.b64 {%0, %1}, %2;" : "=r"(a), "=r"(b) : "l"(v));
    lo = __uint_as_float(a);
    hi = __uint_as_float(b);
}

// ---------------- QKV projection: C = h @ W^T + b (x scale for Q) -----------
// blockIdx.z: 0 -> Q (scale 0.25), 1 -> K, 2 -> V
// 128x128 output tile per block, BK=16, 256 threads, 8x8 microtile, f32x2 FMA.
__global__ __launch_bounds__(256, 2) void qkv_gemm(
    const float* __restrict__ hmat,
    const float* __restrict__ Wq, const float* __restrict__ bq,
    const float* __restrict__ Wk, const float* __restrict__ bk,
    const float* __restrict__ Wv, const float* __restrict__ bv,
    int N)
{
    const int z = blockIdx.z;
    const float* __restrict__ W    = (z == 0) ? Wq : (z == 1) ? Wk : Wv;
    const float* __restrict__ bias = (z == 0) ? bq : (z == 1) ? bk : bv;
    float* __restrict__ C          = (z == 0) ? g_Q : (z == 1) ? g_K : g_V;
    const float scale = (z == 0) ? 0.25f : 1.0f;   // head_dim^-0.5 = 16^-0.5

    __shared__ __align__(16) float As[16][132];    // [k][m], padded
    __shared__ __align__(16) float Bs[16][132];    // [k][n], padded

    const int tid  = threadIdx.x;
    const int row0 = blockIdx.x * 128;
    const int lr   = tid >> 2;          // 0..63
    const int lc   = (tid & 3) * 4;     // 0,4,8,12
    const int tx   = tid & 15;
    const int ty   = tid >> 4;

    unsigned long long acc[8][4];
#pragma unroll
    for (int i = 0; i < 8; i++)
#pragma unroll
        for (int j = 0; j < 4; j++) acc[i][j] = 0ULL;

    for (int kk = 0; kk < 128; kk += 16) {
#pragma unroll
        for (int half = 0; half < 2; half++) {
            int r = lr + half * 64;
            int grow = row0 + r;
            float4 av = make_float4(0.f, 0.f, 0.f, 0.f);
            if (grow < N)
                av = *reinterpret_cast<const float4*>(hmat + (size_t)grow * H + kk + lc);
            As[lc + 0][r] = av.x; As[lc + 1][r] = av.y;
            As[lc + 2][r] = av.z; As[lc + 3][r] = av.w;
            float4 wv = *reinterpret_cast<const float4*>(W + (size_t)r * H + kk + lc);
            Bs[lc + 0][r] = wv.x; Bs[lc + 1][r] = wv.y;
            Bs[lc + 2][r] = wv.z; Bs[lc + 3][r] = wv.w;
        }
        __syncthreads();

#pragma unroll
        for (int k = 0; k < 16; k++) {
            unsigned long long b2[4];
            const unsigned long long* brow =
                reinterpret_cast<const unsigned long long*>(&Bs[k][tx * 8]);
#pragma unroll
            for (int j = 0; j < 4; j++) b2[j] = brow[j];
#pragma unroll
            for (int i = 0; i < 8; i++) {
                unsigned long long ad = dup2(As[k][ty * 8 + i]);
#pragma unroll
                for (int j = 0; j < 4; j++) acc[i][j] = fma2(ad, b2[j], acc[i][j]);
            }
        }
        __syncthreads();
    }

    // epilogue: add bias, scale, store
#pragma unroll
    for (int i = 0; i < 8; i++) {
        int gr = row0 + ty * 8 + i;
        if (gr >= N) continue;
        float* crow = C + (size_t)gr * H + tx * 8;
#pragma unroll
        for (int j = 0; j < 4; j++) {
            float lo, hi;
            unpack2(acc[i][j], lo, hi);
            int c0 = tx * 8 + 2 * j;
            crow[2 * j + 0] = (lo + bias[c0 + 0]) * scale;
            crow[2 * j + 1] = (hi + bias[c0 + 1]) * scale;
        }
    }
}

// ---------------- fused sparse attention ------------------------------------
// One node per 128-thread group (NPB nodes per 512-thread block).
// Layout note: feature f belongs to head f % 8 (reshape(n, head_dim, num_heads)).
__global__ __launch_bounds__(128 * NPB) void attn_kernel(
    const int* __restrict__ row_ptr,
    const int* __restrict__ col_ind,
    float* __restrict__ out,
    int N)
{
    __shared__ float qs[NPB][H];
    __shared__ int   cols[NPB][MAXDEG];
    __shared__ float sc[NPB][MAXDEG][NH];

    const int t  = threadIdx.x;
    const int li = t >> 7;        // local node 0..NPB-1
    const int tt = t & 127;       // thread within node group
    const int i  = blockIdx.x * NPB + li;
    const bool active = (i < N);
    const int ic = active ? i : (N - 1);

    const int start = row_ptr[ic];
    int deg = row_ptr[ic + 1] - start;
    if (deg > MAXDEG) deg = MAXDEG;

    qs[li][tt] = g_Q[(size_t)ic * H + tt];           // Q already scaled
    if (tt < MAXDEG)
        cols[li][tt] = (tt < deg) ? col_ind[start + tt] : 0;
    __syncthreads();

    // scores: thread (el, hd): dot over d of q[d*8+hd] * k[col][d*8+hd]
    const int el = tt >> 3;
    const int hd = tt & 7;
    float s = __int_as_float(0xff800000);            // -inf for padded edges
    if (el < deg) {
        const float* kr = g_K + (size_t)cols[li][el] * H;
        s = 0.0f;
#pragma unroll
        for (int d = 0; d < HDIM; d++)
            s += qs[li][d * NH + hd] * __ldg(kr + d * NH + hd);
    }
    sc[li][el][hd] = s;
    __syncthreads();

    // softmax over edges, per head (8 threads per node)
    if (tt < NH) {
        float m = __int_as_float(0xff800000);
#pragma unroll
        for (int e = 0; e < MAXDEG; e++) m = fmaxf(m, sc[li][e][tt]);
        float ex[MAXDEG];
        float sum = 0.0f;
#pragma unroll
        for (int e = 0; e < MAXDEG; e++) {
            ex[e] = __expf(sc[li][e][tt] - m);       // exp(-inf)=0 for padding
            sum += ex[e];
        }
        float r = __frcp_rn(sum);
#pragma unroll
        for (int e = 0; e < MAXDEG; e++) sc[li][e][tt] = ex[e] * r;
    }
    __syncthreads();

    // bspmm: out[f] = sum_e attn[e, f%8] * v[col_e, f]  (coalesced V reads)
    float acc = 0.0f;
#pragma unroll
    for (int e = 0; e < MAXDEG; e++) {
        acc += sc[li][e][hd] * __ldg(g_V + (size_t)cols[li][e] * H + tt);
    }
    if (active) out[(size_t)i * H + tt] = acc;
}

// ---------------- launch ------------------------------------------------------
extern "C" void kernel_launch(void* const* d_in, const int* in_sizes, int n_in,
                              void* d_out, int out_size) {
    const float* h   = (const float*)d_in[0];
    const float* Wq  = (const float*)d_in[1];
    const float* bq  = (const float*)d_in[2];
    const float* Wk  = (const float*)d_in[3];
    const float* bk  = (const float*)d_in[4];
    const float* Wv  = (const float*)d_in[5];
    const float* bv  = (const float*)d_in[6];
    const int* row_ptr = (const int*)d_in[7];
    const int* col_ind = (const int*)d_in[8];
    float* out = (float*)d_out;

    const int N = in_sizes[0] / H;

    dim3 ggrid((N + 127) / 128, 1, 3);
    qkv_gemm<<<ggrid, 256>>>(h, Wq, bq, Wk, bk, Wv, bv, N);

    const int ablocks = (N + NPB - 1) / NPB;
    attn_kernel<<<ablocks, 128 * NPB>>>(row_ptr, col_ind, out, N);
}